// round 6
// baseline (speedup 1.0000x reference)
#include <cuda_runtime.h>
#include <math.h>

#define NPTS   8192
#define MPTS   8192
#define NB     16
#define WIDTH  32
#define NSPLIT 38
#define TILE_J 128
#define IBLK   256
#define REC    24          // per-source record: x,y,z,wrho, cut[4], bp_perm[16]
#define NBINS  32768       // 32^3 Morton bins

__device__ float g_packed[NPTS * REC];
__device__ float g_heg[NB];
__device__ float g_partial[(size_t)NSPLIT * MPTS * NB];
__device__ int   g_beta_isum[NB];
__device__ int   g_cperm[NB];      // slot k -> original channel
__device__ int   g_hist[NBINS];
__device__ int   g_binstart[NBINS];
__device__ int   g_obin[MPTS];
__device__ int   g_operm[MPTS];    // sorted position -> original output index

// ---- raw MUFU helpers ----
__device__ __forceinline__ float f_ex2(float x) {
    float r; asm("ex2.approx.f32 %0, %1;" : "=f"(r) : "f"(x)); return r;
}
__device__ __forceinline__ float f_lg2(float x) {
    float r; asm("lg2.approx.f32 %0, %1;" : "=f"(r) : "f"(x)); return r;
}
__device__ __forceinline__ float f_rcp(float x) {
    float r; asm("rcp.approx.f32 %0, %1;" : "=f"(r) : "f"(x)); return r;
}
__device__ __forceinline__ float fast_tanh(float a) {
    float u = f_ex2(2.885390081777927f * a);   // exp(2a)
    return fmaf(-2.0f, f_rcp(u + 1.0f), 1.0f);
}
__device__ __forceinline__ float fast_log_cosh(float t) {
    const float LN2 = 0.69314718055994531f;
    float a = fabsf(t);
    float v = f_ex2(-2.885390081777927f * a);  // exp(-2a)
    return fmaf(f_lg2(1.0f + v), LN2, a - LN2);
}

__global__ void zero_kernel() {
    int i = blockIdx.x * blockDim.x + threadIdx.x;
    if (i < NBINS) g_hist[i] = 0;
    if (i < NB)    g_beta_isum[i] = 0;
}

// Warp-per-point setup: lane k owns hidden unit k; WIDTH->NB via SHFL;
// lane b<16 owns basis b. Writes bp in ORIGINAL channel order at slots 8..23.
__global__ void __launch_bounds__(256)
setup_kernel(const float* __restrict__ rho,
             const float* __restrict__ gamma,
             const float* __restrict__ coords,
             const float* __restrict__ weights,
             const float* __restrict__ w1,
             const float* __restrict__ b1,
             const float* __restrict__ w2,
             const float* __restrict__ b2) {
    __shared__ float s_w2[WIDTH * NB];
    int tid = threadIdx.x;
    for (int v = tid; v < WIDTH * NB; v += blockDim.x) s_w2[v] = w2[v];
    __syncthreads();

    int lane = tid & 31;
    int warp = tid >> 5;
    int j = blockIdx.x * (blockDim.x >> 5) + warp;
    if (j >= NPTS) return;

    const float C     = 38.283120002509214f;   // 4*(3*pi^2)^(2/3)
    const float LOG2E = 1.44269504088896340f;
    const float LN2   = 0.69314718055994531f;

    float r = rho[j];
    float l = f_lg2(r);
    float r83 = r * r * f_ex2(l * (2.0f / 3.0f));          // r^(8/3)
    float s2 = gamma[j] * f_rcp(C * r83);
    float x = f_lg2(s2 + 1e-4f) * LN2;

    float h = fast_tanh(fmaf(x, w1[lane], b1[lane]));

    int bl = lane & (NB - 1);
    float o = b2[bl];
#pragma unroll
    for (int k = 0; k < WIDTH; k++) {
        float hk = __shfl_sync(0xffffffffu, h, k);
        o = fmaf(hk, s_w2[k * NB + bl], o);
    }

    float pref = 3.14159265358979323846f * f_ex2((l - 1.0f) * (2.0f / 3.0f));
    float beta = pref * fast_log_cosh(o);
    float bp = -beta * LOG2E;

    if (lane < NB) {
        g_packed[j * REC + 8 + lane] = bp;
        // deterministic channel-magnitude stats (order-independent int atomics)
        atomicAdd(&g_beta_isum[lane], (int)(fminf(beta, 64.0f) * 256.0f));
    }
    if (lane == 16) g_packed[j * REC + 0] = coords[j * 3 + 0];
    if (lane == 17) g_packed[j * REC + 1] = coords[j * 3 + 1];
    if (lane == 18) g_packed[j * REC + 2] = coords[j * 3 + 2];
    if (lane == 19) g_packed[j * REC + 3] = weights[j] * r;

    if (j == 0) {
        float h0 = fast_tanh(b1[lane]);
        float o0 = b2[bl];
#pragma unroll
        for (int k = 0; k < WIDTH; k++) {
            float hk = __shfl_sync(0xffffffffu, h0, k);
            o0 = fmaf(hk, s_w2[k * NB + bl], o0);
        }
        if (lane < NB) {
            float lc = fast_log_cosh(o0);
            g_heg[lane] = lc * sqrtf(lc);
        }
    }
}

// Argsort channels by summed beta ascending (group 0 = longest-range channels).
__global__ void cperm_kernel() {
    if (threadIdx.x == 0 && blockIdx.x == 0) {
        int idx[NB];
        for (int k = 0; k < NB; k++) idx[k] = k;
        for (int a = 0; a < NB - 1; a++) {
            int mn = a;
            for (int b = a + 1; b < NB; b++)
                if (g_beta_isum[idx[b]] < g_beta_isum[idx[mn]]) mn = b;
            int t = idx[a]; idx[a] = idx[mn]; idx[mn] = t;
        }
        for (int k = 0; k < NB; k++) g_cperm[k] = idx[k];
    }
}

// Per-source: permute bp into sorted-channel order, compute 4 suffix-max d2
// cutoffs (exactness: ex2 and reference expf both give 0.0f past the cutoff).
__global__ void finalize_kernel() {
    int j = blockIdx.x * blockDim.x + threadIdx.x;
    if (j >= NPTS) return;
    int cp[NB];
#pragma unroll
    for (int k = 0; k < NB; k++) cp[k] = g_cperm[k];
    float bp[NB], pb[NB];
#pragma unroll
    for (int k = 0; k < NB; k++) bp[k] = g_packed[j * REC + 8 + k];
#pragma unroll
    for (int k = 0; k < NB; k++) pb[k] = bp[cp[k]];
    float cuts[4];
    float cm = 0.0f;
#pragma unroll
    for (int k = NB - 1; k >= 0; k--) {
        float c = (pb[k] < -1e-30f) ? (-128.0f / pb[k]) : 1e30f;
        cm = fmaxf(cm, c);
        if ((k & 3) == 0) cuts[k >> 2] = cm;
    }
#pragma unroll
    for (int k = 0; k < NB; k++) g_packed[j * REC + 8 + k] = pb[k];
#pragma unroll
    for (int g = 0; g < 4; g++) g_packed[j * REC + 4 + g] = cuts[g];
}

// ---- deterministic spatial sort of output points (Morton bins) ----
__device__ __forceinline__ unsigned expand3(unsigned v) {
    v &= 31u;
    v = (v | (v << 8)) & 0x100Fu;
    v = (v | (v << 4)) & 0x10C3u;
    v = (v | (v << 2)) & 0x1249u;
    return v;
}

__global__ void bin_kernel(const float* __restrict__ out_coords) {
    int i = blockIdx.x * blockDim.x + threadIdx.x;
    if (i >= MPTS) return;
    float x = out_coords[i * 3 + 0];
    float y = out_coords[i * 3 + 1];
    float z = out_coords[i * 3 + 2];
    int bx = min(max((int)((x + 20.0f) * 0.8f), 0), 31);
    int by = min(max((int)((y + 20.0f) * 0.8f), 0), 31);
    int bz = min(max((int)((z + 20.0f) * 0.8f), 0), 31);
    unsigned m = expand3(bx) | (expand3(by) << 1) | (expand3(bz) << 2);
    g_obin[i] = (int)m;
    atomicAdd(&g_hist[m], 1);
}

__global__ void __launch_bounds__(1024)
scan_kernel() {
    __shared__ int sa[1024], sb[1024];
    int t = threadIdx.x;
    int base = t * 32;
    int loc[32];
    int tot = 0;
#pragma unroll
    for (int k = 0; k < 32; k++) { loc[k] = tot; tot += g_hist[base + k]; }
    sa[t] = tot;
    __syncthreads();
    int* src = sa; int* dst = sb;
    for (int d = 1; d < 1024; d <<= 1) {
        dst[t] = src[t] + ((t >= d) ? src[t - d] : 0);
        __syncthreads();
        int* tmp = src; src = dst; dst = tmp;
    }
    int excl = src[t] - tot;   // exclusive prefix of this thread's chunk
#pragma unroll
    for (int k = 0; k < 32; k++) g_binstart[base + k] = excl + loc[k];
}

// Stable rank: warp per point counts same-bin predecessors.
__global__ void __launch_bounds__(256)
rank_kernel() {
    int lane = threadIdx.x & 31;
    int wid = (blockIdx.x * blockDim.x + threadIdx.x) >> 5;
    if (wid >= MPTS) return;
    int mybin = g_obin[wid];
    int cnt = 0;
    for (int q = lane; q < wid; q += 32)
        cnt += (g_obin[q] == mybin) ? 1 : 0;
#pragma unroll
    for (int d = 16; d > 0; d >>= 1)
        cnt += __shfl_down_sync(0xffffffffu, cnt, d);
    if (lane == 0) g_operm[g_binstart[mybin] + cnt] = wid;
}

#define GRP(G)                                                              \
    {                                                                       \
        float e0, e1, e2, e3;                                               \
        asm("ex2.approx.f32 %0, %1;" : "=f"(e0) : "f"(p[8 + 4*G + 0] * d2)); \
        asm("ex2.approx.f32 %0, %1;" : "=f"(e1) : "f"(p[8 + 4*G + 1] * d2)); \
        asm("ex2.approx.f32 %0, %1;" : "=f"(e2) : "f"(p[8 + 4*G + 2] * d2)); \
        asm("ex2.approx.f32 %0, %1;" : "=f"(e3) : "f"(p[8 + 4*G + 3] * d2)); \
        acc[4*G + 0] = fmaf(e0, w, acc[4*G + 0]);                           \
        acc[4*G + 1] = fmaf(e1, w, acc[4*G + 1]);                           \
        acc[4*G + 2] = fmaf(e2, w, acc[4*G + 2]);                           \
        acc[4*G + 3] = fmaf(e3, w, acc[4*G + 3]);                           \
    }

__global__ void __launch_bounds__(IBLK)
main_kernel(const float* __restrict__ out_coords) {
    __shared__ float tile[TILE_J * REC];

    int ilin = blockIdx.x * IBLK + threadIdx.x;
    int i = g_operm[ilin];
    int split = blockIdx.y;

    float ox = out_coords[i * 3 + 0];
    float oy = out_coords[i * 3 + 1];
    float oz = out_coords[i * 3 + 2];

    float acc[NB];
#pragma unroll
    for (int b = 0; b < NB; b++) acc[b] = 0.0f;

    int jbeg = (split * NPTS) / NSPLIT;
    int jend = ((split + 1) * NPTS) / NSPLIT;

    for (int t = jbeg; t < jend; t += TILE_J) {
        int cnt = min(TILE_J, jend - t);
        __syncthreads();
        {
            const float4* src = (const float4*)(g_packed + (size_t)t * REC);
            float4* dst = (float4*)tile;
            int nvec = cnt * (REC / 4);
            for (int v = threadIdx.x; v < nvec; v += IBLK) dst[v] = src[v];
        }
        __syncthreads();

        for (int jt = 0; jt < cnt; ++jt) {
            const float* p = tile + jt * REC;
            float4 cw = *(const float4*)p;        // x, y, z, wrho
            float4 ct = *(const float4*)(p + 4);  // group cutoffs (desc)
            float dx = ox - cw.x;
            float dy = oy - cw.y;
            float dz = oz - cw.z;
            float d2 = fmaf(dx, dx, fmaf(dy, dy, dz * dz));
            float w = cw.w;
            // channels sorted by beta ascending; cutoffs are suffix maxima,
            // so d2 >= ct.x means ALL channels flush to exactly 0.
            if (d2 < ct.x) {
                GRP(0)
                if (d2 < ct.y) {
                    GRP(1)
                    if (d2 < ct.z) {
                        GRP(2)
                        if (d2 < ct.w) {
                            GRP(3)
                        }
                    }
                }
            }
        }
    }

    float* outp = g_partial + ((size_t)split * MPTS + ilin) * NB;
#pragma unroll
    for (int b = 0; b < NB; b++) outp[b] = acc[b];
}

__global__ void reduce_kernel(float* __restrict__ out) {
    int idx = blockIdx.x * blockDim.x + threadIdx.x;  // ilin*NB + k
    if (idx >= MPTS * NB) return;
    int k = idx & (NB - 1);
    int ilin = idx >> 4;
    float s = 0.0f;
#pragma unroll
    for (int sp = 0; sp < NSPLIT; sp++)
        s += g_partial[(size_t)sp * (MPTS * NB) + idx];
    int b = g_cperm[k];
    int io = g_operm[ilin];
    out[io * NB + b] = s * g_heg[b];
}

extern "C" void kernel_launch(void* const* d_in, const int* in_sizes, int n_in,
                              void* d_out, int out_size) {
    const float* rho        = (const float*)d_in[0];
    const float* gamma      = (const float*)d_in[1];
    const float* coords     = (const float*)d_in[2];
    const float* weights    = (const float*)d_in[3];
    const float* out_coords = (const float*)d_in[4];
    const float* w1         = (const float*)d_in[5];
    const float* b1         = (const float*)d_in[6];
    const float* w2         = (const float*)d_in[7];
    const float* b2         = (const float*)d_in[8];
    float* out = (float*)d_out;

    zero_kernel<<<(NBINS + 255) / 256, 256>>>();
    setup_kernel<<<NPTS / 8, 256>>>(rho, gamma, coords, weights,
                                    w1, b1, w2, b2);
    cperm_kernel<<<1, 32>>>();
    finalize_kernel<<<(NPTS + 255) / 256, 256>>>();
    bin_kernel<<<(MPTS + 255) / 256, 256>>>(out_coords);
    scan_kernel<<<1, 1024>>>();
    rank_kernel<<<MPTS / 8, 256>>>();
    dim3 grid(MPTS / IBLK, NSPLIT);
    main_kernel<<<grid, IBLK>>>(out_coords);
    reduce_kernel<<<(MPTS * NB + 255) / 256, 256>>>(out);
}

// round 7
// speedup vs baseline: 1.2531x; 1.2531x over previous
#include <cuda_runtime.h>
#include <math.h>

#define NPTS   8192
#define MPTS   8192
#define NB     16
#define WIDTH  32
#define NSPLIT 19
#define TILE_J 128
#define IBLK   256

// Per-source packed record: x, y, z, wrho, bp[16]  (bp = -beta * log2(e))
__device__ float g_packed[NPTS * 20];
__device__ float g_heg[NB];
__device__ float g_partial[(size_t)NSPLIT * MPTS * NB];

// ---- raw MUFU helpers ----
__device__ __forceinline__ float f_ex2(float x) {
    float r; asm("ex2.approx.f32 %0, %1;" : "=f"(r) : "f"(x)); return r;
}
__device__ __forceinline__ float f_lg2(float x) {
    float r; asm("lg2.approx.f32 %0, %1;" : "=f"(r) : "f"(x)); return r;
}
__device__ __forceinline__ float f_rcp(float x) {
    float r; asm("rcp.approx.f32 %0, %1;" : "=f"(r) : "f"(x)); return r;
}
__device__ __forceinline__ float fast_tanh(float a) {
    float u = f_ex2(2.885390081777927f * a);   // exp(2a)
    return fmaf(-2.0f, f_rcp(u + 1.0f), 1.0f);
}
__device__ __forceinline__ float fast_log_cosh(float t) {
    const float LN2 = 0.69314718055994531f;
    float a = fabsf(t);
    float v = f_ex2(-2.885390081777927f * a);  // exp(-2a)
    return fmaf(f_lg2(1.0f + v), LN2, a - LN2);
}

// Warp-per-point setup: lane k owns hidden unit k; WIDTH->NB layer via
// 32 SHFL broadcasts; lane b<16 owns basis b.
__global__ void __launch_bounds__(256)
setup_kernel(const float* __restrict__ rho,
             const float* __restrict__ gamma,
             const float* __restrict__ coords,
             const float* __restrict__ weights,
             const float* __restrict__ w1,
             const float* __restrict__ b1,
             const float* __restrict__ w2,
             const float* __restrict__ b2) {
    __shared__ float s_w2[WIDTH * NB];
    int tid = threadIdx.x;
    for (int v = tid; v < WIDTH * NB; v += blockDim.x) s_w2[v] = w2[v];
    __syncthreads();

    int lane = tid & 31;
    int warp = tid >> 5;
    int j = blockIdx.x * (blockDim.x >> 5) + warp;
    if (j >= NPTS) return;

    const float C     = 38.283120002509214f;   // 4*(3*pi^2)^(2/3)
    const float LOG2E = 1.44269504088896340f;
    const float LN2   = 0.69314718055994531f;

    float r = rho[j];
    float l = f_lg2(r);
    float r83 = r * r * f_ex2(l * (2.0f / 3.0f));          // r^(8/3)
    float s2 = gamma[j] * f_rcp(C * r83);
    float x = f_lg2(s2 + 1e-4f) * LN2;                     // log(s2+eps)

    // hidden layer: one tanh per lane
    float h = fast_tanh(fmaf(x, w1[lane], b1[lane]));

    // output layer: lane b (b<16) accumulates o_b
    int bl = lane & (NB - 1);
    float o = b2[bl];
#pragma unroll
    for (int k = 0; k < WIDTH; k++) {
        float hk = __shfl_sync(0xffffffffu, h, k);
        o = fmaf(hk, s_w2[k * NB + bl], o);
    }

    float pref = 3.14159265358979323846f * f_ex2((l - 1.0f) * (2.0f / 3.0f));
    float bp = -pref * fast_log_cosh(o) * LOG2E;

    if (lane < NB) g_packed[j * 20 + 4 + lane] = bp;
    if (lane == 16) g_packed[j * 20 + 0] = coords[j * 3 + 0];
    if (lane == 17) g_packed[j * 20 + 1] = coords[j * 3 + 1];
    if (lane == 18) g_packed[j * 20 + 2] = coords[j * 3 + 2];
    if (lane == 19) g_packed[j * 20 + 3] = weights[j] * r;

    if (j == 0) {
        // heg_scale: field_embed at x = 0
        float h0 = fast_tanh(b1[lane]);
        float o0 = b2[bl];
#pragma unroll
        for (int k = 0; k < WIDTH; k++) {
            float hk = __shfl_sync(0xffffffffu, h0, k);
            o0 = fmaf(hk, s_w2[k * NB + bl], o0);
        }
        if (lane < NB) {
            float lc = fast_log_cosh(o0);
            g_heg[lane] = lc * sqrtf(lc);                  // lc^1.5
        }
    }
}

__global__ void __launch_bounds__(IBLK)
main_kernel(const float* __restrict__ out_coords) {
    __shared__ float tile[TILE_J * 20];

    int i = blockIdx.x * IBLK + threadIdx.x;
    int split = blockIdx.y;

    float ox = out_coords[i * 3 + 0];
    float oy = out_coords[i * 3 + 1];
    float oz = out_coords[i * 3 + 2];

    float acc[NB];
#pragma unroll
    for (int b = 0; b < NB; b++) acc[b] = 0.0f;

    int jbeg = (split * NPTS) / NSPLIT;
    int jend = ((split + 1) * NPTS) / NSPLIT;

    for (int t = jbeg; t < jend; t += TILE_J) {
        int cnt = min(TILE_J, jend - t);
        __syncthreads();
        {
            const float4* src = (const float4*)(g_packed + (size_t)t * 20);
            float4* dst = (float4*)tile;
            int nvec = cnt * 5;  // 20 floats = 5 float4 per j
            for (int v = threadIdx.x; v < nvec; v += IBLK) dst[v] = src[v];
        }
        __syncthreads();

        for (int jt = 0; jt < cnt; ++jt) {
            const float* p = tile + jt * 20;
            float4 cw = *(const float4*)p;  // x, y, z, wrho
            float dx = ox - cw.x;
            float dy = oy - cw.y;
            float dz = oz - cw.z;
            float d2 = fmaf(dx, dx, fmaf(dy, dy, dz * dz));
            float w = cw.w;
#pragma unroll
            for (int b = 0; b < NB; b++) {
                float e;
                float arg = p[4 + b] * d2;  // -beta*log2e*d2
                asm("ex2.approx.f32 %0, %1;" : "=f"(e) : "f"(arg));
                acc[b] = fmaf(e, w, acc[b]);
            }
        }
    }

    float* outp = g_partial + ((size_t)split * MPTS + i) * NB;
#pragma unroll
    for (int b = 0; b < NB; b++) outp[b] = acc[b];
}

__global__ void reduce_kernel(float* __restrict__ out) {
    int idx = blockIdx.x * blockDim.x + threadIdx.x;  // i*NB + b
    if (idx >= MPTS * NB) return;
    int b = idx & (NB - 1);
    float s = 0.0f;
#pragma unroll
    for (int sp = 0; sp < NSPLIT; sp++)
        s += g_partial[(size_t)sp * (MPTS * NB) + idx];
    out[idx] = s * g_heg[b];
}

extern "C" void kernel_launch(void* const* d_in, const int* in_sizes, int n_in,
                              void* d_out, int out_size) {
    const float* rho        = (const float*)d_in[0];
    const float* gamma      = (const float*)d_in[1];
    const float* coords     = (const float*)d_in[2];
    const float* weights    = (const float*)d_in[3];
    const float* out_coords = (const float*)d_in[4];
    const float* w1         = (const float*)d_in[5];
    const float* b1         = (const float*)d_in[6];
    const float* w2         = (const float*)d_in[7];
    const float* b2         = (const float*)d_in[8];
    float* out = (float*)d_out;

    setup_kernel<<<NPTS / 8, 256>>>(rho, gamma, coords, weights,
                                    w1, b1, w2, b2);
    dim3 grid(MPTS / IBLK, NSPLIT);
    main_kernel<<<grid, IBLK>>>(out_coords);
    reduce_kernel<<<(MPTS * NB + 255) / 256, 256>>>(out);
}